// round 12
// baseline (speedup 1.0000x reference)
#include <cuda_runtime.h>

// Problem constants
#define NN 50000
#define EE 800000
#define FF 128
#define HH 256
#define GG 512
#define TT 4

// ---------------- scratch (device globals) ----------------------------------
__device__ __align__(16) float g_dinv[NN];
__device__ __align__(16) float g_buf1[(size_t)NN * HH];
__device__ __align__(16) float g_buf2[(size_t)NN * HH];
__device__ __align__(16) float g_sums[GG * HH];
__device__ int g_deg[NN];
__device__ int g_rowstart[NN + 1];
__device__ int g_cursor[NN];
__device__ int g_csr[EE];
__device__ int g_gcnt[GG];
__device__ int g_goff[GG + 1];

// ---------------- small helpers (R3 verbatim) --------------------------------
static __device__ __forceinline__ float4 f4scale(float4 v, float s) {
    return make_float4(v.x * s, v.y * s, v.z * s, v.w * s);
}
static __device__ __forceinline__ void f4fma(float4& a, float4 v, float s) {
    a.x += v.x * s; a.y += v.y * s; a.z += v.z * s; a.w += v.w * s;
}

// ---------------- degree / counts (R3 verbatim) ------------------------------
__global__ void k_zero_counts() {
    int i = blockIdx.x * blockDim.x + threadIdx.x;
    if (i < NN) g_deg[i] = 0;
    if (i < GG) g_gcnt[i] = 0;
}

__global__ void k_deg(const int* __restrict__ ei) {
    int e = blockIdx.x * blockDim.x + threadIdx.x;
    if (e < EE) atomicAdd(&g_deg[ei[EE + e]], 1);
}

__global__ void k_ghist(const int* __restrict__ batch) {
    int n = blockIdx.x * blockDim.x + threadIdx.x;
    if (n < NN) atomicAdd(&g_gcnt[batch[n]], 1);
}

__global__ void k_fin_dinv() {
    int n = blockIdx.x * blockDim.x + threadIdx.x;
    if (n < NN) g_dinv[n] = rsqrtf((float)(g_deg[n] + 1));  // +1 self loop
}

// ---------------- one-block scans (R3 verbatim) ------------------------------
__global__ void k_scan_nodes() {
    __shared__ int ssum[1024];
    int t = threadIdx.x;
    const int CH = (NN + 1023) / 1024;
    int lo = t * CH, hi = min(lo + CH, NN);
    int s = 0;
    for (int i = lo; i < hi; i++) s += g_deg[i];
    ssum[t] = s;
    __syncthreads();
    for (int off = 1; off < 1024; off <<= 1) {
        int v = (t >= off) ? ssum[t - off] : 0;
        __syncthreads();
        ssum[t] += v;
        __syncthreads();
    }
    int run = (t > 0) ? ssum[t - 1] : 0;
    for (int i = lo; i < hi; i++) {
        g_rowstart[i] = run;
        g_cursor[i] = run;
        run += g_deg[i];
    }
    if (t == 0) g_rowstart[NN] = EE;
}

__global__ void k_scan_graphs() {
    __shared__ int s[GG];
    int t = threadIdx.x;
    int mine = g_gcnt[t];
    s[t] = mine;
    __syncthreads();
    for (int off = 1; off < GG; off <<= 1) {
        int v = (t >= off) ? s[t - off] : 0;
        __syncthreads();
        s[t] += v;
        __syncthreads();
    }
    g_goff[t] = s[t] - mine;  // exclusive
    if (t == 0) g_goff[GG] = NN;
}

__global__ void k_scatter(const int* __restrict__ ei) {
    int e = blockIdx.x * blockDim.x + threadIdx.x;
    if (e >= EE) return;
    int d = ei[EE + e];
    int p = atomicAdd(&g_cursor[d], 1);
    g_csr[p] = ei[e];
}

// ---------------- CSR aggregation (R3 verbatim): one warp per dst node -------
// out[d] = dinv[d] * ( in[d]*dinv[d] + sum_{s in nbr(d)} in[s]*dinv[s] )
template<int F4>   // F4 = DIM/128
__global__ void k_agg_csr(const float* __restrict__ in, float* __restrict__ out) {
    int w = (blockIdx.x * blockDim.x + threadIdx.x) >> 5;
    if (w >= NN) return;
    int lane = threadIdx.x & 31;
    const int DIM = F4 * 128;

    float dd = g_dinv[w];
    float4 acc[F4];
    const float4* self = (const float4*)(in + (size_t)w * DIM);
#pragma unroll
    for (int i = 0; i < F4; i++) acc[i] = f4scale(self[lane + i * 32], dd);

    int e = g_rowstart[w];
    int e1 = g_rowstart[w + 1];
    for (; e + 1 < e1; e += 2) {
        int s0 = g_csr[e], s1 = g_csr[e + 1];
        float d0 = g_dinv[s0], d1 = g_dinv[s1];
        const float4* r0 = (const float4*)(in + (size_t)s0 * DIM);
        const float4* r1 = (const float4*)(in + (size_t)s1 * DIM);
#pragma unroll
        for (int i = 0; i < F4; i++) {
            float4 v0 = r0[lane + i * 32];
            float4 v1 = r1[lane + i * 32];
            f4fma(acc[i], v0, d0);
            f4fma(acc[i], v1, d1);
        }
    }
    if (e < e1) {
        int s0 = g_csr[e];
        float d0 = g_dinv[s0];
        const float4* r0 = (const float4*)(in + (size_t)s0 * DIM);
#pragma unroll
        for (int i = 0; i < F4; i++) f4fma(acc[i], r0[lane + i * 32], d0);
    }

    float4* o = (float4*)(out + (size_t)w * DIM);
#pragma unroll
    for (int i = 0; i < F4; i++) o[lane + i * 32] = f4scale(acc[i], dd);
}

// ---------------- SGEMM (R10-verified 128x128/8x8) + fused bias+relu ---------
// C[M,256] = relu(A[M,K] @ B[K,256] + bias)
template<int K>
__global__ void __launch_bounds__(256) k_gemm(const float* __restrict__ A,
                                              const float* __restrict__ B,
                                              const float* __restrict__ bias,
                                              float* __restrict__ C) {
    __shared__ float As[16][128];   // transposed: As[k][m]
    __shared__ float Bs[16][128];   // Bs[k][n]

    const int tid = threadIdx.x;
    const int tx = tid & 15;
    const int ty = tid >> 4;
    const int m0 = blockIdx.y * 128;
    const int n0 = blockIdx.x * 128;

    float acc[8][8];
#pragma unroll
    for (int i = 0; i < 8; i++)
#pragma unroll
        for (int j = 0; j < 8; j++) acc[i][j] = 0.0f;

    const int ra = tid >> 2;          // 0..63
    const int ca = (tid & 3) * 4;     // 0,4,8,12
    const int rb = tid >> 5;          // 0..7
    const int cb = (tid & 31) * 4;    // 0..124

    for (int k0 = 0; k0 < K; k0 += 16) {
#pragma unroll
        for (int it = 0; it < 2; it++) {
            int r = ra + it * 64;
            float4 av;
            if (m0 + r < NN)
                av = *(const float4*)(A + (size_t)(m0 + r) * K + k0 + ca);
            else
                av = make_float4(0.f, 0.f, 0.f, 0.f);
            As[ca + 0][r] = av.x;
            As[ca + 1][r] = av.y;
            As[ca + 2][r] = av.z;
            As[ca + 3][r] = av.w;
        }
#pragma unroll
        for (int it = 0; it < 2; it++) {
            int r = rb + it * 8;
            *(float4*)&Bs[r][cb] = *(const float4*)(B + (size_t)(k0 + r) * HH + n0 + cb);
        }
        __syncthreads();

#pragma unroll
        for (int k = 0; k < 16; k++) {
            float4 a0 = *(const float4*)&As[k][ty * 8];
            float4 a1 = *(const float4*)&As[k][ty * 8 + 4];
            float4 b0 = *(const float4*)&Bs[k][tx * 8];
            float4 b1 = *(const float4*)&Bs[k][tx * 8 + 4];
            float ar[8] = { a0.x, a0.y, a0.z, a0.w, a1.x, a1.y, a1.z, a1.w };
            float br[8] = { b0.x, b0.y, b0.z, b0.w, b1.x, b1.y, b1.z, b1.w };
#pragma unroll
            for (int i = 0; i < 8; i++)
#pragma unroll
                for (int j = 0; j < 8; j++)
                    acc[i][j] += ar[i] * br[j];
        }
        __syncthreads();
    }

    float4 bb0 = *(const float4*)(bias + n0 + tx * 8);
    float4 bb1 = *(const float4*)(bias + n0 + tx * 8 + 4);
#pragma unroll
    for (int i = 0; i < 8; i++) {
        int m = m0 + ty * 8 + i;
        if (m < NN) {
            float4 v0, v1;
            v0.x = fmaxf(acc[i][0] + bb0.x, 0.0f);
            v0.y = fmaxf(acc[i][1] + bb0.y, 0.0f);
            v0.z = fmaxf(acc[i][2] + bb0.z, 0.0f);
            v0.w = fmaxf(acc[i][3] + bb0.w, 0.0f);
            v1.x = fmaxf(acc[i][4] + bb1.x, 0.0f);
            v1.y = fmaxf(acc[i][5] + bb1.y, 0.0f);
            v1.z = fmaxf(acc[i][6] + bb1.z, 0.0f);
            v1.w = fmaxf(acc[i][7] + bb1.w, 0.0f);
            *(float4*)(C + (size_t)m * HH + n0 + tx * 8)     = v0;
            *(float4*)(C + (size_t)m * HH + n0 + tx * 8 + 4) = v1;
        }
    }
}

// ---------------- segmented pool (R3 verbatim) -------------------------------
__global__ void k_pool_seg(const float* __restrict__ in) {
    int g = blockIdx.x;
    int c = threadIdx.x;                 // 256
    int lo = g_goff[g], hi = g_goff[g + 1];
    float acc = 0.0f;
    for (int n = lo; n < hi; n++) acc += in[(size_t)n * HH + c];
    g_sums[g * HH + c] = acc;
}

// ---------------- MLP head (R3 verbatim) -------------------------------------
__global__ void k_head(const float* __restrict__ na,
                       const float* __restrict__ W3, const float* __restrict__ b3,
                       const float* __restrict__ W4, const float* __restrict__ b4,
                       float* __restrict__ out) {
    int g = blockIdx.x;
    int j = threadIdx.x;   // 32 threads
    __shared__ float zsh[32];

    float cnt = (float)(g_goff[g + 1] - g_goff[g]);
    float inv = 1.0f / fmaxf(cnt, 1.0f);
    float acc = b3[j];
#pragma unroll 8
    for (int k = 0; k < HH; k++)
        acc += (g_sums[g * HH + k] * inv) * W3[k * 32 + j];
    acc += na[g] * W3[HH * 32 + j];
    zsh[j] = fmaxf(acc, 0.0f);
    __syncthreads();

    if (j < TT) {
        float o = b4[j];
#pragma unroll
        for (int t = 0; t < 32; t++) o += zsh[t] * W4[t * TT + j];
        out[g * TT + j] = o;
    }
}

// ---------------- launch -----------------------------------------------------
extern "C" void kernel_launch(void* const* d_in, const int* in_sizes, int n_in,
                              void* d_out, int out_size) {
    const float* x     = (const float*)d_in[0];
    const int*   ei    = (const int*)  d_in[1];
    const int*   batch = (const int*)  d_in[2];
    const float* na    = (const float*)d_in[3];
    const float* W1    = (const float*)d_in[4];
    const float* b1    = (const float*)d_in[5];
    const float* W2    = (const float*)d_in[6];
    const float* b2    = (const float*)d_in[7];
    const float* W3    = (const float*)d_in[8];
    const float* b3    = (const float*)d_in[9];
    const float* W4    = (const float*)d_in[10];
    const float* b4    = (const float*)d_in[11];
    float* out = (float*)d_out;

    const int agg_blocks = (NN * 32 + 255) / 256;
    dim3 gemm_grid(HH / 128, (NN + 127) / 128);

    // CSR build + normalization (idx 3 = k_scan_nodes -> profiled)
    k_zero_counts<<<(NN + 255) / 256, 256>>>();
    k_deg<<<(EE + 255) / 256, 256>>>(ei);
    k_fin_dinv<<<(NN + 255) / 256, 256>>>();
    k_scan_nodes<<<1, 1024>>>();
    k_scatter<<<(EE + 255) / 256, 256>>>(ei);

    // Layer 1: aggregate x (128-dim) first, then GEMM with fused bias+relu
    k_agg_csr<1><<<agg_blocks, 256>>>(x, g_buf2);
    k_gemm<FF><<<gemm_grid, 256>>>(g_buf2, W1, b1, g_buf1);

    // graph offsets (needed only before pool)
    k_ghist<<<(NN + 255) / 256, 256>>>(batch);
    k_scan_graphs<<<1, GG>>>();

    // Layer 2: aggregate h1 (256-dim), then GEMM with fused bias+relu
    k_agg_csr<2><<<agg_blocks, 256>>>(g_buf1, g_buf2);
    k_gemm<HH><<<gemm_grid, 256>>>(g_buf2, W2, b2, g_buf1);

    // Pool + head
    k_pool_seg<<<GG, HH>>>(g_buf1);
    k_head<<<GG, 32>>>(na, W3, b3, W4, b4, out);
}

// round 15
// speedup vs baseline: 10.3271x; 10.3271x over previous
#include <cuda_runtime.h>
#include <cuda_bf16.h>

// Problem constants (fixed shapes for this problem instance)
#define NN 50000
#define EE 800000
#define FF 128
#define HH 256
#define GG 512
#define TT 4

// ---------------- scratch (device globals: no allocation allowed) ----------
__device__ __align__(16) float g_dinv[NN];
__device__ __align__(16) float g_buf1[(size_t)NN * HH];   // GEMM outputs
__device__ __align__(16) float g_buf2[(size_t)NN * HH];   // agg / activations
__device__ __align__(16) float g_sums[GG * HH];
__device__ float g_cnt[GG];

// ---------------- degree / normalization ----------------------------------
__global__ void k_init_dinv() {
    int n = blockIdx.x * blockDim.x + threadIdx.x;
    if (n < NN) g_dinv[n] = 1.0f;   // self-loop contributes 1 to degree
}

__global__ void k_deg(const int* __restrict__ ei) {
    int e = blockIdx.x * blockDim.x + threadIdx.x;
    if (e < EE) atomicAdd(&g_dinv[ei[EE + e]], 1.0f);   // dst row
}

__global__ void k_fin_dinv() {
    int n = blockIdx.x * blockDim.x + threadIdx.x;
    if (n < NN) g_dinv[n] = rsqrtf(g_dinv[n]);          // deg >= 1 always
}

// ---------------- zero kernels ---------------------------------------------
__global__ void k_zero_buf2() {
    int i = blockIdx.x * blockDim.x + threadIdx.x;
    int stride = gridDim.x * blockDim.x;
    float4* p = (float4*)g_buf2;
    const int n4 = (NN * HH) / 4;
    for (int j = i; j < n4; j += stride) p[j] = make_float4(0.f, 0.f, 0.f, 0.f);
}

__global__ void k_zero_pool() {
    int i = blockIdx.x * blockDim.x + threadIdx.x;
    if (i < GG * HH) g_sums[i] = 0.0f;
    if (i < GG) g_cnt[i] = 0.0f;
}

// ---------------- SGEMM: C[M,256] = A[M,K] @ B[K,256] ----------------------
// 128x128 tile, BK=16, 256 threads, 8x8 microtile per thread.
// B-columns per thread: [tx*4, tx*4+4) and [64+tx*4, 64+tx*4+4) — 16 B lane
// stride, conflict-free LDS phases (the old tx*8 mapping was 2-way conflicted).
template<int K, bool SRC_BUF2>
__global__ void __launch_bounds__(256) k_gemm(const float* __restrict__ Aarg,
                                              const float* __restrict__ B) {
    const float* __restrict__ A = SRC_BUF2 ? (const float*)g_buf2 : Aarg;
    float* __restrict__ C = g_buf1;

    __shared__ float As[16][128];   // transposed: As[k][m]
    __shared__ float Bs[16][128];   // Bs[k][n]

    const int tid = threadIdx.x;
    const int tx = tid & 15;        // 16 col-groups
    const int ty = tid >> 4;        // 16 row-groups of 8
    const int m0 = blockIdx.y * 128;
    const int n0 = blockIdx.x * 128;

    float acc[8][8];
#pragma unroll
    for (int i = 0; i < 8; i++)
#pragma unroll
        for (int j = 0; j < 8; j++) acc[i][j] = 0.0f;

    // loader mappings (each thread loads 2 float4 of A, 2 float4 of B)
    const int ra = tid >> 2;          // 0..63  (A row base; +64 on 2nd iter)
    const int ca = (tid & 3) * 4;     // k offset 0,4,8,12
    const int rb = tid >> 5;          // 0..7   (B row base; +8 on 2nd iter)
    const int cb = (tid & 31) * 4;    // col 0..124

    for (int k0 = 0; k0 < K; k0 += 16) {
#pragma unroll
        for (int it = 0; it < 2; it++) {
            int r = ra + it * 64;
            float4 av;
            if (m0 + r < NN)
                av = *(const float4*)(A + (size_t)(m0 + r) * K + k0 + ca);
            else
                av = make_float4(0.f, 0.f, 0.f, 0.f);
            As[ca + 0][r] = av.x;
            As[ca + 1][r] = av.y;
            As[ca + 2][r] = av.z;
            As[ca + 3][r] = av.w;
        }
#pragma unroll
        for (int it = 0; it < 2; it++) {
            int r = rb + it * 8;
            *(float4*)&Bs[r][cb] = *(const float4*)(B + (size_t)(k0 + r) * HH + n0 + cb);
        }
        __syncthreads();

#pragma unroll
        for (int k = 0; k < 16; k++) {
            float4 a0 = *(const float4*)&As[k][ty * 8];
            float4 a1 = *(const float4*)&As[k][ty * 8 + 4];
            float4 b0 = *(const float4*)&Bs[k][tx * 4];        // cols tx*4..+3
            float4 b1 = *(const float4*)&Bs[k][64 + tx * 4];   // cols 64+tx*4..+3
            float ar[8] = { a0.x, a0.y, a0.z, a0.w, a1.x, a1.y, a1.z, a1.w };
            float br[8] = { b0.x, b0.y, b0.z, b0.w, b1.x, b1.y, b1.z, b1.w };
#pragma unroll
            for (int i = 0; i < 8; i++)
#pragma unroll
                for (int j = 0; j < 8; j++)
                    acc[i][j] += ar[i] * br[j];
        }
        __syncthreads();
    }

#pragma unroll
    for (int i = 0; i < 8; i++) {
        int m = m0 + ty * 8 + i;
        if (m < NN) {
            float4 v0 = make_float4(acc[i][0], acc[i][1], acc[i][2], acc[i][3]);
            float4 v1 = make_float4(acc[i][4], acc[i][5], acc[i][6], acc[i][7]);
            *(float4*)(C + (size_t)m * HH + n0 + tx * 4)      = v0;   // cols tx*4
            *(float4*)(C + (size_t)m * HH + n0 + 64 + tx * 4) = v1;   // cols 64+tx*4
        }
    }
}

// ---------------- edge aggregation: agg[dst] += h[src] * norm --------------
// One warp per edge; float4 vector atomics (sm_90+) keep us on the LTS byte cap.
__global__ void k_agg(const int* __restrict__ ei) {
    int w = (blockIdx.x * blockDim.x + threadIdx.x) >> 5;
    int lane = threadIdx.x & 31;
    if (w >= EE) return;
    int s = ei[w];
    int d = ei[EE + w];
    float nrm = g_dinv[s] * g_dinv[d];
    const float4* __restrict__ hs = (const float4*)(g_buf1 + (size_t)s * HH);
    float4* __restrict__ ad = (float4*)(g_buf2 + (size_t)d * HH);
#pragma unroll
    for (int i = 0; i < 2; i++) {
        int c = lane + i * 32;       // 0..63 float4s = 256 floats
        float4 v = hs[c];
        atomicAdd(&ad[c], make_float4(v.x * nrm, v.y * nrm, v.z * nrm, v.w * nrm));
    }
}

// ---------------- self-loop + bias + relu (in place into buf2) -------------
__global__ void k_post(const float* __restrict__ b) {
    int n = blockIdx.x;
    int c = threadIdx.x;
    float di = g_dinv[n];
    size_t idx = (size_t)n * HH + c;
    float v = g_buf2[idx] + g_buf1[idx] * (di * di) + b[c];
    g_buf2[idx] = fmaxf(v, 0.0f);
}

// ---------------- global mean pool -----------------------------------------
__global__ void k_pool(const int* __restrict__ batch) {
    int n = blockIdx.x;
    int c = threadIdx.x;
    int g = batch[n];
    atomicAdd(&g_sums[g * HH + c], g_buf2[(size_t)n * HH + c]);
    if (c == 0) atomicAdd(&g_cnt[g], 1.0f);
}

// ---------------- MLP head: relu(concat(pooled, na) @ W3 + b3) @ W4 + b4 ---
__global__ void k_head(const float* __restrict__ na,
                       const float* __restrict__ W3, const float* __restrict__ b3,
                       const float* __restrict__ W4, const float* __restrict__ b4,
                       float* __restrict__ out) {
    int g = blockIdx.x;
    int j = threadIdx.x;   // 32 threads, one per hidden unit
    __shared__ float zsh[32];

    float inv = 1.0f / fmaxf(g_cnt[g], 1.0f);
    float acc = b3[j];
#pragma unroll 8
    for (int k = 0; k < HH; k++)
        acc += (g_sums[g * HH + k] * inv) * W3[k * 32 + j];
    acc += na[g] * W3[HH * 32 + j];   // num_atoms feature (row 256 of W3)
    zsh[j] = fmaxf(acc, 0.0f);
    __syncthreads();

    if (j < TT) {
        float o = b4[j];
#pragma unroll
        for (int t = 0; t < 32; t++) o += zsh[t] * W4[t * TT + j];
        out[g * TT + j] = o;
    }
}

// ---------------- launch ----------------------------------------------------
extern "C" void kernel_launch(void* const* d_in, const int* in_sizes, int n_in,
                              void* d_out, int out_size) {
    const float* x     = (const float*)d_in[0];
    const int*   ei    = (const int*)  d_in[1];
    const int*   batch = (const int*)  d_in[2];
    const float* na    = (const float*)d_in[3];
    const float* W1    = (const float*)d_in[4];
    const float* b1    = (const float*)d_in[5];
    const float* W2    = (const float*)d_in[6];
    const float* b2    = (const float*)d_in[7];
    const float* W3    = (const float*)d_in[8];
    const float* b3    = (const float*)d_in[9];
    const float* W4    = (const float*)d_in[10];
    const float* b4    = (const float*)d_in[11];
    float* out = (float*)d_out;

    // degree -> dinv (idx 0-2)
    k_init_dinv<<<(NN + 255) / 256, 256>>>();
    k_deg<<<(EE + 255) / 256, 256>>>(ei);
    k_fin_dinv<<<(NN + 255) / 256, 256>>>();

    dim3 gemm_grid(HH / 128, (NN + 127) / 128);

    // idx 3: layer-1 GEMM — ncu profiles this launch
    k_gemm<FF, false><<<gemm_grid, 256>>>(x, W1);

    // Layer 1: zero ; agg ; relu(agg + selfloop + b1)
    k_zero_buf2<<<1024, 256>>>();
    k_agg<<<((size_t)EE * 32 + 255) / 256, 256>>>(ei);
    k_post<<<NN, 256>>>(b1);

    // Layer 2: h = a1 @ W2 ; zero ; agg ; relu(agg + selfloop + b2)
    k_gemm<HH, true><<<gemm_grid, 256>>>(nullptr, W2);
    k_zero_buf2<<<1024, 256>>>();
    k_agg<<<((size_t)EE * 32 + 255) / 256, 256>>>(ei);
    k_post<<<NN, 256>>>(b2);

    // Pool + head
    k_zero_pool<<<(GG * HH + 255) / 256, 256>>>();
    k_pool<<<NN, 256>>>(batch);
    k_head<<<GG, 32>>>(na, W3, b3, W4, b4, out);
}